// round 8
// baseline (speedup 1.0000x reference)
#include <cuda_runtime.h>
#include <cstdint>

// Problem dims
#define B_ 32
#define P_ 12
#define N_ 512
#define F_ 64
#define D_ 256
#define Q_ 12
#define DT_ 0.1f

static const int BQN = B_ * Q_ * N_;  // 196608
#define NBQ (B_ * Q_)                 // 384

// ---------------- scratch (device globals; no runtime alloc) ----------------
__device__ float g_tmp  [(size_t)B_ * Q_ * N_ * F_];     // mixed inputs (tf32 bits)
__device__ float g_h    [(size_t)B_ * Q_ * N_ * D_];     // hidden (tf32 bits)
__device__ float g_qkv  [(size_t)B_ * Q_ * N_ * 3 * D_]; // q|k|v, ld=768 (tf32 bits)
__device__ float g_S    [(size_t)B_ * Q_ * N_ * N_];     // exp'd partial P (fp32)
__device__ float g_CP   [(size_t)12 * N_ * N_];          // c_k = (I+DT*A)^k - I, tf32
__device__ float g_WinT [(size_t)D_ * F_];               // W_in^T  tf32
__device__ float g_WqkvT[(size_t)3 * D_ * D_];           // Wqkv^T  tf32
__device__ float g_WoutT[(size_t)F_ * D_];               // W_out^T tf32
__device__ float g_pmax [(size_t)NBQ * 4 * N_];          // per-(bq,colblk,row)
__device__ float g_psum [(size_t)NBQ * 4 * N_];
__device__ float g_fac  [(size_t)NBQ * 4 * N_];

// ---------------- helpers ----------------------------------------------------
__device__ __forceinline__ uint32_t f2tf32(float f) {
    uint32_t u;
    asm("cvt.rna.tf32.f32 %0, %1;" : "=r"(u) : "f"(f));
    return u;
}
__device__ __forceinline__ float roundtf(float f) { return __uint_as_float(f2tf32(f)); }

__device__ __forceinline__ void mma_tf32(float* c, const uint32_t* a, const uint32_t* b) {
    asm volatile(
        "mma.sync.aligned.m16n8k8.row.col.f32.tf32.tf32.f32 "
        "{%0,%1,%2,%3}, {%4,%5,%6,%7}, {%8,%9}, {%0,%1,%2,%3};"
        : "+f"(c[0]), "+f"(c[1]), "+f"(c[2]), "+f"(c[3])
        : "r"(a[0]), "r"(a[1]), "r"(a[2]), "r"(a[3]),
          "r"(b[0]), "r"(b[1]));
}

__device__ __forceinline__ void ldsm_x4(uint32_t* r, uint32_t addr) {
    asm volatile("ldmatrix.sync.aligned.m8n8.x4.shared.b16 {%0,%1,%2,%3}, [%4];"
                 : "=r"(r[0]), "=r"(r[1]), "=r"(r[2]), "=r"(r[3]) : "r"(addr));
}

__device__ __forceinline__ void cp_async16(uint32_t smem_dst, const void* gsrc) {
    asm volatile("cp.async.cg.shared.global [%0], [%1], 16;\n" :: "r"(smem_dst), "l"(gsrc));
}

// ---------------- K1: tmp = time-mix(inputs), tf32-rounded -------------------
__global__ __launch_bounds__(256) void mix_kernel(const float* __restrict__ in,
                                                  const float* __restrict__ T) {
    __shared__ float Ts[P_][Q_];
    int t = threadIdx.x;
    if (t < P_ * Q_) Ts[t / Q_][t % Q_] = T[t];
    __syncthreads();
    long idx = (long)blockIdx.x * blockDim.x + t;
    if (idx >= (long)B_ * N_ * F_) return;
    int f = (int)(idx % F_);
    int n = (int)((idx / F_) % N_);
    int b = (int)(idx / ((long)F_ * N_));
    float vals[P_];
    const float* ip = in + ((long)b * P_ * N_ + n) * F_ + f;
#pragma unroll
    for (int p = 0; p < P_; p++) vals[p] = ip[(long)p * N_ * F_];
    float* op = g_tmp + ((long)b * Q_ * N_ + n) * F_ + f;
#pragma unroll
    for (int q = 0; q < Q_; q++) {
        float s = 0.f;
#pragma unroll
        for (int p = 0; p < P_; p++) s += vals[p] * Ts[p][q];
        op[(long)q * N_ * F_] = roundtf(s);
    }
}

// ---------------- setup: transposed + rounded weights, c1 --------------------
__global__ __launch_bounds__(256) void prep_weights(const float* __restrict__ Win,
                                                    const float* __restrict__ Wq,
                                                    const float* __restrict__ Wk,
                                                    const float* __restrict__ Wv,
                                                    const float* __restrict__ Wout) {
    int i = blockIdx.x * blockDim.x + threadIdx.x;
    if (i < D_ * D_) {
        int r = i / D_, c = i % D_;
        g_WqkvT[(long)c * D_ + r]            = roundtf(Wq[i] * 0.0625f);
        g_WqkvT[(long)(D_ + c) * D_ + r]     = roundtf(Wk[i]);
        g_WqkvT[(long)(2 * D_ + c) * D_ + r] = roundtf(Wv[i]);
    }
    if (i < F_ * D_) {
        int r = i / D_, c = i % D_;
        g_WinT[(long)c * F_ + r] = roundtf(Win[i]);
    }
    if (i < D_ * F_) {
        int r = i / F_, c = i % F_;
        g_WoutT[(long)c * D_ + r] = roundtf(Wout[i]);
    }
}

__global__ __launch_bounds__(256) void scaleA_kernel(const float* __restrict__ A) {
    int i = blockIdx.x * blockDim.x + threadIdx.x;
    if (i < N_ * N_) g_CP[i] = roundtf(DT_ * A[i]);
}

// ---------------- softmax stats combiner (2 col-blocks of 256) ---------------
__global__ __launch_bounds__(256) void combine_stats() {
    long idx = (long)blockIdx.x * 256 + threadIdx.x;
    if (idx >= (long)NBQ * N_) return;
    int bq = (int)(idx >> 9), row = (int)(idx & (N_ - 1));
    float pm[2], ps[2];
#pragma unroll
    for (int b = 0; b < 2; b++) {
        pm[b] = g_pmax[((long)bq * 2 + b) * N_ + row];
        ps[b] = g_psum[((long)bq * 2 + b) * N_ + row];
    }
    float m = fmaxf(pm[0], pm[1]);
    float e0 = __expf(pm[0] - m), e1 = __expf(pm[1] - m);
    float inv = 1.f / (ps[0] * e0 + ps[1] * e1);
    g_fac[((long)bq * 2 + 0) * N_ + row] = e0 * inv;
    g_fac[((long)bq * 2 + 1) * N_ + row] = e1 * inv;
}

// ---------------- tf32 tensor-core GEMM: cp.async x3 + ldmatrix --------------
// C = alpha*A*op(B) + beta*R (RESID) + R2[row%512] (RESID2)
// STATS: epilogue emits per-(row, col-block) softmax stats; stores exp'd vals.
// SMAX:  A fragments scaled by fac[bz][blk][row], block width = SBN cols.
template <int BM, int BN, int WM, int WN, bool TRANS_B, bool RESID, int RMOD,
          bool CVT_A, bool CVT_B, bool ROUND_C, bool STATS, bool SMAX, bool RESID2,
          int SBN, int OCC>
__global__ __launch_bounds__(WM* WN * 32, OCC) void gemm_tc(
    const float* __restrict__ A, const float* __restrict__ Bm,
    float* __restrict__ C, const float* __restrict__ R,
    const float* __restrict__ R2, float* __restrict__ pmaxg,
    float* __restrict__ psumg, const float* __restrict__ fac,
    int M, int Nn, int K, int lda, int ldb, int ldc, int ldr,
    long sA, long sB, long sC, long sR, float alpha, float beta) {
    constexpr int BK = 16;
    constexpr int STAGES = 3;
    constexpr int NTH = WM * WN * 32;
    constexpr int WTM = BM / WM;           // 64
    constexpr int WTN = BN / WN;           // 64 (big) / 32 (small)
    constexpr int FM = WTM / 16;           // 4
    constexpr int FN = WTN / 8;            // 8 / 4
    constexpr int LDA_S = BK + 4;          // 20 words
    constexpr int LDB_S = BN + 8;
    constexpr int NA = BM * BK / (4 * NTH);
    constexpr int NB = BN * BK / (4 * NTH);
    constexpr int A_STAGE_B = BM * LDA_S * 4;
    constexpr int BT_STAGE_B = BN * LDA_S * 4;
    constexpr int BN_STAGE_B = BK * LDB_S * 4;
    constexpr int SBT = SBN / BK;          // k-tiles per stats block

    extern __shared__ __align__(16) float smem[];
    float* Bs_ = smem + STAGES * BM * LDA_S;
    const uint32_t smem_u32 = (uint32_t)__cvta_generic_to_shared(smem);
    const uint32_t bs_u32 = smem_u32 + STAGES * A_STAGE_B;

    const int bz = blockIdx.z;
    A += (long)bz * sA;
    Bm += (long)bz * sB;
    C += (long)bz * sC;
    if (RESID) R += (long)bz * sR;

    const int row0 = blockIdx.y * BM, col0 = blockIdx.x * BN;
    const int tid = threadIdx.x;
    const int lane = tid & 31, wid = tid >> 5;
    const int grp = lane >> 2, qid = lane & 3;
    const int wm = wid / WN, wn = wid % WN;
    const int m_base = wm * WTM, n_base = wn * WTN;

    const int mi = lane >> 3, rr = lane & 7;
    const uint32_t aAddr0 = smem_u32 +
        (((m_base + ((mi & 1) << 3) + rr) * LDA_S + ((mi >> 1) << 2)) << 2);
    const uint32_t bAddr0 = bs_u32 +
        (((n_base + ((mi >> 1) << 3) + rr) * LDA_S + ((mi & 1) << 2)) << 2);

    float acc[FM][FN][4] = {};
    float facr[FM][2];

    auto issue = [&](int st, int k0) {
#pragma unroll
        for (int l = 0; l < NA; l++) {
            int i = tid + l * NTH;
            int r = i >> 2, kq = i & 3;
            cp_async16(smem_u32 + st * A_STAGE_B + ((r * LDA_S + kq * 4) << 2),
                       A + (long)(row0 + r) * lda + k0 + kq * 4);
        }
#pragma unroll
        for (int l = 0; l < NB; l++) {
            int i = tid + l * NTH;
            if (!TRANS_B) {
                int kk = i / (BN / 4), nq = i % (BN / 4);
                cp_async16(bs_u32 + st * BN_STAGE_B + ((kk * LDB_S + nq * 4) << 2),
                           Bm + (long)(k0 + kk) * ldb + col0 + nq * 4);
            } else {
                int n = i >> 2, kq = i & 3;
                cp_async16(bs_u32 + st * BT_STAGE_B + ((n * LDA_S + kq * 4) << 2),
                           Bm + (long)(col0 + n) * ldb + k0 + kq * 4);
            }
        }
    };

    const int kt = K / BK;
#pragma unroll
    for (int s = 0; s < STAGES - 1; s++) {
        issue(s, s * BK);
        asm volatile("cp.async.commit_group;\n");
    }

    for (int t = 0; t < kt; t++) {
        asm volatile("cp.async.wait_group %0;\n" :: "n"(STAGES - 2));
        __syncthreads();
        const int st = t % STAGES;
        const int nx = t + STAGES - 1;
        if (nx < kt) issue(nx % STAGES, nx * BK);
        asm volatile("cp.async.commit_group;\n");

        if (SMAX) {
            if ((t % SBT) == 0) {
                int blk = t / SBT;
                long fb = ((long)bz * (K / SBN) + blk) * M + row0 + m_base + grp;
#pragma unroll
                for (int i = 0; i < FM; i++) {
                    facr[i][0] = fac[fb + i * 16];
                    facr[i][1] = fac[fb + i * 16 + 8];
                }
            }
        }

        const uint32_t aSt = aAddr0 + st * A_STAGE_B;
        const uint32_t bSt = bAddr0 + st * BT_STAGE_B;

#pragma unroll
        for (int kc = 0; kc < 2; kc++) {
            const int kk = kc * 8;
            uint32_t af[FM][4], bf[FN][2];
#pragma unroll
            for (int i = 0; i < FM; i++) {
                ldsm_x4(af[i], aSt + i * (16 * LDA_S * 4) + kc * 32);
                if (SMAX) {
                    af[i][0] = f2tf32(__uint_as_float(af[i][0]) * facr[i][0]);
                    af[i][1] = f2tf32(__uint_as_float(af[i][1]) * facr[i][1]);
                    af[i][2] = f2tf32(__uint_as_float(af[i][2]) * facr[i][0]);
                    af[i][3] = f2tf32(__uint_as_float(af[i][3]) * facr[i][1]);
                } else if (CVT_A) {
#pragma unroll
                    for (int q = 0; q < 4; q++) af[i][q] = f2tf32(__uint_as_float(af[i][q]));
                }
            }
            if (TRANS_B) {
#pragma unroll
                for (int jp = 0; jp < FN / 2; jp++) {
                    uint32_t tmp4[4];
                    ldsm_x4(tmp4, bSt + jp * (16 * LDA_S * 4) + kc * 32);
                    if (CVT_B) {
#pragma unroll
                        for (int q = 0; q < 4; q++) tmp4[q] = f2tf32(__uint_as_float(tmp4[q]));
                    }
                    bf[jp * 2][0] = tmp4[0]; bf[jp * 2][1] = tmp4[1];
                    bf[jp * 2 + 1][0] = tmp4[2]; bf[jp * 2 + 1][1] = tmp4[3];
                }
            } else {
#pragma unroll
                for (int j = 0; j < FN; j++) {
                    int n = n_base + j * 8 + grp;
                    float b0 = Bs_[(st * BK + kk + qid) * LDB_S + n];
                    float b1 = Bs_[(st * BK + kk + qid + 4) * LDB_S + n];
                    bf[j][0] = CVT_B ? f2tf32(b0) : __float_as_uint(b0);
                    bf[j][1] = CVT_B ? f2tf32(b1) : __float_as_uint(b1);
                }
            }
#pragma unroll
            for (int i = 0; i < FM; i++)
#pragma unroll
                for (int j = 0; j < FN; j++) mma_tf32(acc[i][j], af[i], bf[j]);
        }
    }

    // ---- STATS: block softmax (exp w.r.t. block max) + partial stats --------
    if (STATS) {
        asm volatile("cp.async.wait_group 0;\n");
        __syncthreads();
        float* red = smem;   // [WN][BM]
        float rmax[FM][2];
#pragma unroll
        for (int i = 0; i < FM; i++)
#pragma unroll
            for (int h = 0; h < 2; h++) {
                float lm = -1e30f;
#pragma unroll
                for (int j = 0; j < FN; j++) {
                    acc[i][j][2 * h] *= alpha;
                    acc[i][j][2 * h + 1] *= alpha;
                    lm = fmaxf(lm, fmaxf(acc[i][j][2 * h], acc[i][j][2 * h + 1]));
                }
                lm = fmaxf(lm, __shfl_xor_sync(0xffffffffu, lm, 1));
                lm = fmaxf(lm, __shfl_xor_sync(0xffffffffu, lm, 2));
                if (qid == 0) red[wn * BM + m_base + i * 16 + grp + h * 8] = lm;
            }
        __syncthreads();
#pragma unroll
        for (int i = 0; i < FM; i++)
#pragma unroll
            for (int h = 0; h < 2; h++) {
                int rl = m_base + i * 16 + grp + h * 8;
                float m0 = red[rl];
#pragma unroll
                for (int w = 1; w < WN; w++) m0 = fmaxf(m0, red[w * BM + rl]);
                rmax[i][h] = m0;
            }
        __syncthreads();
#pragma unroll
        for (int i = 0; i < FM; i++)
#pragma unroll
            for (int h = 0; h < 2; h++) {
                float ls = 0.f;
#pragma unroll
                for (int j = 0; j < FN; j++) {
                    float p0 = __expf(acc[i][j][2 * h] - rmax[i][h]);
                    float p1 = __expf(acc[i][j][2 * h + 1] - rmax[i][h]);
                    acc[i][j][2 * h] = p0;
                    acc[i][j][2 * h + 1] = p1;
                    ls += p0 + p1;
                }
                ls += __shfl_xor_sync(0xffffffffu, ls, 1);
                ls += __shfl_xor_sync(0xffffffffu, ls, 2);
                if (qid == 0) red[wn * BM + m_base + i * 16 + grp + h * 8] = ls;
            }
        __syncthreads();
        long sbase = ((long)bz * gridDim.x + blockIdx.x) * M + row0;
#pragma unroll
        for (int i = 0; i < FM; i++)
#pragma unroll
            for (int h = 0; h < 2; h++) {
                int rl = m_base + i * 16 + grp + h * 8;
                if (wn == 0 && qid == 0) {
                    float s = 0.f;
#pragma unroll
                    for (int w = 0; w < WN; w++) s += red[w * BM + rl];
                    pmaxg[sbase + rl] = rmax[i][h];
                    psumg[sbase + rl] = s;
                }
            }
    }

    // ---- epilogue ----
#pragma unroll
    for (int i = 0; i < FM; i++) {
        int r0 = row0 + m_base + i * 16 + grp;
#pragma unroll
        for (int j = 0; j < FN; j++) {
            int c = col0 + n_base + j * 8 + qid * 2;
            float2 v0, v1;
            if (STATS) {
                v0 = {acc[i][j][0], acc[i][j][1]};
                v1 = {acc[i][j][2], acc[i][j][3]};
            } else {
                v0 = {acc[i][j][0] * alpha, acc[i][j][1] * alpha};
                v1 = {acc[i][j][2] * alpha, acc[i][j][3] * alpha};
            }
            if (RESID) {
                int rr0 = RMOD ? (r0 % RMOD) : r0;
                int rr1 = RMOD ? ((r0 + 8) % RMOD) : (r0 + 8);
                float2 r0v = *(const float2*)(R + (long)rr0 * ldr + c);
                float2 r1v = *(const float2*)(R + (long)rr1 * ldr + c);
                v0.x += beta * r0v.x; v0.y += beta * r0v.y;
                v1.x += beta * r1v.x; v1.y += beta * r1v.y;
            }
            if (RESID2) {
                float2 a0 = *(const float2*)(R2 + (long)(r0 % N_) * N_ + c);
                float2 a1 = *(const float2*)(R2 + (long)((r0 + 8) % N_) * N_ + c);
                v0.x += a0.x; v0.y += a0.y;
                v1.x += a1.x; v1.y += a1.y;
            }
            if (ROUND_C) {
                v0.x = roundtf(v0.x); v0.y = roundtf(v0.y);
                v1.x = roundtf(v1.x); v1.y = roundtf(v1.y);
            }
            *(float2*)(C + (long)r0 * ldc + c) = v0;
            *(float2*)(C + (long)(r0 + 8) * ldc + c) = v1;
        }
    }
}

// host-side smem size mirror
static inline int gemm_smem_bytes(int BM, int BN, bool transB) {
    const int STAGES = 3, BK = 16, LDA_S = 20;
    int a = STAGES * BM * LDA_S;
    int b = transB ? STAGES * BN * LDA_S : STAGES * BK * (BN + 8);
    return (a + b) * 4;
}

// ---------------- launch ----------------------------------------------------
extern "C" void kernel_launch(void* const* d_in, const int* in_sizes, int n_in,
                              void* d_out, int out_size) {
    const float* inputs = (const float*)d_in[0];
    const float* W_in  = (const float*)d_in[2];
    const float* T_mix = (const float*)d_in[3];
    const float* Wq    = (const float*)d_in[4];
    const float* Wk    = (const float*)d_in[5];
    const float* Wv    = (const float*)d_in[6];
    const float* W_out = (const float*)d_in[7];
    const float* A     = (const float*)d_in[8];

    float* out = (float*)d_out;
    float* mgt = out;
    float* kal = out + (long)B_ * Q_ * N_ * F_;

    float *tmp, *h, *qkv, *S, *CP, *WinT, *WqkvT, *WoutT, *pmax, *psum, *fac;
    cudaGetSymbolAddress((void**)&tmp, g_tmp);
    cudaGetSymbolAddress((void**)&h, g_h);
    cudaGetSymbolAddress((void**)&qkv, g_qkv);
    cudaGetSymbolAddress((void**)&S, g_S);
    cudaGetSymbolAddress((void**)&CP, g_CP);
    cudaGetSymbolAddress((void**)&WinT, g_WinT);
    cudaGetSymbolAddress((void**)&WqkvT, g_WqkvT);
    cudaGetSymbolAddress((void**)&WoutT, g_WoutT);
    cudaGetSymbolAddress((void**)&pmax, g_pmax);
    cudaGetSymbolAddress((void**)&psum, g_psum);
    cudaGetSymbolAddress((void**)&fac, g_fac);

    const long sNN = (long)N_ * N_;
    const long sNF = (long)N_ * F_;
    const long sQKV = (long)N_ * 3 * D_;
    const long sH = (long)N_ * D_;

    // Big-tile instances: BM=128, BN=256, 8 warps, warp tile 64x64, 1 CTA/SM
    auto kBIG = gemm_tc<128, 256, 2, 4, true,  false, 0,  false, false, true,  false, false, false, 256, 1>;
    auto kQK  = gemm_tc<128, 256, 2, 4, true,  false, 0,  false, false, false, true,  false, false, 256, 1>;
    auto kAV  = gemm_tc<128, 256, 2, 4, false, true,  0,  false, false, true,  false, true,  false, 256, 1>;
    // Small-tile instances (N=64 shapes, CP chain): 2 CTAs/SM
    auto kOUT = gemm_tc<128, 64,  2, 2, true,  false, 0,  false, false, false, false, false, false, 256, 2>;
    auto kCP  = gemm_tc<128, 128, 2, 4, false, true,  0,  false, false, true,  false, false, true,  256, 2>;
    auto kKAL = gemm_tc<128, 64,  2, 2, false, true,  N_, false, true,  false, false, false, false, 256, 2>;

    const int smBIG_NT = gemm_smem_bytes(128, 256, true);    // 92160
    const int smBIG_NN = gemm_smem_bytes(128, 256, false);
    const int smNN     = gemm_smem_bytes(128, 128, false);
    const int smNT64   = gemm_smem_bytes(128, 64, true);
    const int smNN64   = gemm_smem_bytes(128, 64, false);
    cudaFuncSetAttribute(kBIG, cudaFuncAttributeMaxDynamicSharedMemorySize, smBIG_NT);
    cudaFuncSetAttribute(kQK,  cudaFuncAttributeMaxDynamicSharedMemorySize, smBIG_NT);
    cudaFuncSetAttribute(kAV,  cudaFuncAttributeMaxDynamicSharedMemorySize, smBIG_NN);
    cudaFuncSetAttribute(kOUT, cudaFuncAttributeMaxDynamicSharedMemorySize, smNT64);
    cudaFuncSetAttribute(kCP,  cudaFuncAttributeMaxDynamicSharedMemorySize, smNN);
    cudaFuncSetAttribute(kKAL, cudaFuncAttributeMaxDynamicSharedMemorySize, smNN64);

    // K1 + setup
    mix_kernel<<<((long)B_ * N_ * F_ + 255) / 256, 256>>>(inputs, T_mix);
    prep_weights<<<(D_ * D_ + 255) / 256, 256>>>(W_in, Wq, Wk, Wv, W_out);
    scaleA_kernel<<<(N_ * N_ + 255) / 256, 256>>>(A);   // c1 = tf32(DT*A)

    // CP chain: c_{k+j} = c_k @ c_j + c_k + c_j  (log-depth, 4 launches)
    float* c1 = CP;
    float* c2 = CP + sNN;
    float* c4 = CP + 3 * sNN;
    float* c8 = CP + 7 * sNN;
    kCP<<<dim3(4, 4, 1), 256, smNN>>>(c1, c1, c2, c1, c1, nullptr, nullptr, nullptr,
        N_, N_, N_, N_, N_, N_, N_, 0, 0, 0, 0, 1.f, 1.f);
    kCP<<<dim3(4, 8, 1), 256, smNN>>>(CP, c2, CP + 2 * sNN, CP, c2, nullptr, nullptr, nullptr,
        2 * N_, N_, N_, N_, N_, N_, N_, 0, 0, 0, 0, 1.f, 1.f);
    kCP<<<dim3(4, 16, 1), 256, smNN>>>(CP, c4, CP + 4 * sNN, CP, c4, nullptr, nullptr, nullptr,
        4 * N_, N_, N_, N_, N_, N_, N_, 0, 0, 0, 0, 1.f, 1.f);
    kCP<<<dim3(4, 16, 1), 256, smNN>>>(CP, c8, CP + 8 * sNN, CP, c8, nullptr, nullptr, nullptr,
        4 * N_, N_, N_, N_, N_, N_, N_, 0, 0, 0, 0, 1.f, 1.f);

    // K2: h = tmp @ WinT^T   (N=256 -> one col-block)
    kBIG<<<dim3(1, BQN / 128, 1), 256, smBIG_NT>>>(
        tmp, WinT, h, nullptr, nullptr, nullptr, nullptr, nullptr,
        BQN, D_, F_, F_, F_, D_, 0, 0, 0, 0, 0, 1.f, 0.f);

    // K3: qkv = h @ WqkvT^T  (N=768 -> 3 col-blocks)
    kBIG<<<dim3(3, BQN / 128, 1), 256, smBIG_NT>>>(
        h, WqkvT, qkv, nullptr, nullptr, nullptr, nullptr, nullptr,
        BQN, 3 * D_, D_, D_, D_, 3 * D_, 0, 0, 0, 0, 0, 1.f, 0.f);

    // K4: S = exp(q@k^T - blockmax), per-256-col-block stats (batched NT)
    kQK<<<dim3(2, 4, NBQ), 256, smBIG_NT>>>(
        qkv, qkv + D_, S, nullptr, nullptr, pmax, psum, nullptr,
        N_, N_, D_, 3 * D_, 3 * D_, N_, 0, sQKV, sQKV, sNN, 0, 1.f, 0.f);

    // stats combine -> fac (2 blocks per row)
    combine_stats<<<((long)NBQ * N_ + 255) / 256, 256>>>();

    // K6: h = h + softmax(S) @ v  (A fragments scaled by fac; N=256 full D)
    kAV<<<dim3(1, 4, NBQ), 256, smBIG_NN>>>(
        S, qkv + 2 * D_, h, h, nullptr, nullptr, nullptr, fac,
        N_, D_, N_, N_, 3 * D_, D_, D_, sNN, sQKV, sH, sH, 1.f, 1.f);

    // K7: mgt = h @ WoutT^T
    kOUT<<<dim3(1, BQN / 128, 1), 128, smNT64>>>(
        h, WoutT, mgt, nullptr, nullptr, nullptr, nullptr, nullptr,
        BQN, F_, D_, D_, D_, F_, 0, 0, 0, 0, 0, 1.f, 0.f);

    // Kalman (single parallel launch): kal[b, t] = c_{t+1} @ mu0[b] + mu0[b]
    const float* mu0 = inputs + (long)(P_ - 1) * sNF;
    kKAL<<<dim3(1, 12 * N_ / 128, B_), 128, smNN64>>>(
        CP, mu0, kal, mu0, nullptr, nullptr, nullptr, nullptr,
        12 * N_, F_, N_, N_, F_, F_, F_,
        0, (long)P_ * sNF, (long)Q_ * sNF, (long)P_ * sNF, 1.f, 1.f);
}

// round 9
// speedup vs baseline: 1.1671x; 1.1671x over previous
#include <cuda_runtime.h>
#include <cstdint>

// Problem dims
#define B_ 32
#define P_ 12
#define N_ 512
#define F_ 64
#define D_ 256
#define Q_ 12
#define DT_ 0.1f

static const int BQN = B_ * Q_ * N_;  // 196608
#define NBQ (B_ * Q_)                 // 384

// ---------------- scratch (device globals; no runtime alloc) ----------------
__device__ float g_tmp  [(size_t)B_ * Q_ * N_ * F_];     // mixed inputs (tf32 bits)
__device__ float g_h    [(size_t)B_ * Q_ * N_ * D_];     // hidden (tf32 bits)
__device__ float g_qkv  [(size_t)B_ * Q_ * N_ * 3 * D_]; // q|k|v, ld=768 (tf32 bits)
__device__ float g_S    [(size_t)B_ * Q_ * N_ * N_];     // scores fp32 / attn tf32
__device__ float g_CP   [(size_t)12 * N_ * N_];          // c_k = (I+DT*A)^k - I, tf32
__device__ float g_WinT [(size_t)D_ * F_];               // W_in^T  tf32
__device__ float g_WqkvT[(size_t)3 * D_ * D_];           // Wqkv^T  tf32
__device__ float g_WoutT[(size_t)F_ * D_];               // W_out^T tf32

// ---------------- helpers ----------------------------------------------------
__device__ __forceinline__ uint32_t f2tf32(float f) {
    uint32_t u;
    asm("cvt.rna.tf32.f32 %0, %1;" : "=r"(u) : "f"(f));
    return u;
}
__device__ __forceinline__ float roundtf(float f) { return __uint_as_float(f2tf32(f)); }

__device__ __forceinline__ void mma_tf32(float* c, const uint32_t* a, const uint32_t* b) {
    asm volatile(
        "mma.sync.aligned.m16n8k8.row.col.f32.tf32.tf32.f32 "
        "{%0,%1,%2,%3}, {%4,%5,%6,%7}, {%8,%9}, {%0,%1,%2,%3};"
        : "+f"(c[0]), "+f"(c[1]), "+f"(c[2]), "+f"(c[3])
        : "r"(a[0]), "r"(a[1]), "r"(a[2]), "r"(a[3]),
          "r"(b[0]), "r"(b[1]));
}

__device__ __forceinline__ void ldsm_x4(uint32_t* r, uint32_t addr) {
    asm volatile("ldmatrix.sync.aligned.m8n8.x4.shared.b16 {%0,%1,%2,%3}, [%4];"
                 : "=r"(r[0]), "=r"(r[1]), "=r"(r[2]), "=r"(r[3]) : "r"(addr));
}

__device__ __forceinline__ void cp_async16(uint32_t smem_dst, const void* gsrc) {
    asm volatile("cp.async.cg.shared.global [%0], [%1], 16;\n" :: "r"(smem_dst), "l"(gsrc));
}

// ---------------- K1: tmp = time-mix(inputs), tf32-rounded -------------------
__global__ __launch_bounds__(256) void mix_kernel(const float* __restrict__ in,
                                                  const float* __restrict__ T) {
    __shared__ float Ts[P_][Q_];
    int t = threadIdx.x;
    if (t < P_ * Q_) Ts[t / Q_][t % Q_] = T[t];
    __syncthreads();
    long idx = (long)blockIdx.x * blockDim.x + t;
    if (idx >= (long)B_ * N_ * F_) return;
    int f = (int)(idx % F_);
    int n = (int)((idx / F_) % N_);
    int b = (int)(idx / ((long)F_ * N_));
    float vals[P_];
    const float* ip = in + ((long)b * P_ * N_ + n) * F_ + f;
#pragma unroll
    for (int p = 0; p < P_; p++) vals[p] = ip[(long)p * N_ * F_];
    float* op = g_tmp + ((long)b * Q_ * N_ + n) * F_ + f;
#pragma unroll
    for (int q = 0; q < Q_; q++) {
        float s = 0.f;
#pragma unroll
        for (int p = 0; p < P_; p++) s += vals[p] * Ts[p][q];
        op[(long)q * N_ * F_] = roundtf(s);
    }
}

// ---------------- setup: transposed + rounded weights, c1 --------------------
__global__ __launch_bounds__(256) void prep_weights(const float* __restrict__ Win,
                                                    const float* __restrict__ Wq,
                                                    const float* __restrict__ Wk,
                                                    const float* __restrict__ Wv,
                                                    const float* __restrict__ Wout) {
    int i = blockIdx.x * blockDim.x + threadIdx.x;
    if (i < D_ * D_) {
        int r = i / D_, c = i % D_;
        g_WqkvT[(long)c * D_ + r]            = roundtf(Wq[i] * 0.0625f);
        g_WqkvT[(long)(D_ + c) * D_ + r]     = roundtf(Wk[i]);
        g_WqkvT[(long)(2 * D_ + c) * D_ + r] = roundtf(Wv[i]);
    }
    if (i < F_ * D_) {
        int r = i / D_, c = i % D_;
        g_WinT[(long)c * F_ + r] = roundtf(Win[i]);
    }
    if (i < D_ * F_) {
        int r = i / F_, c = i % F_;
        g_WoutT[(long)c * D_ + r] = roundtf(Wout[i]);
    }
}

__global__ __launch_bounds__(256) void scaleA_kernel(const float* __restrict__ A) {
    int i = blockIdx.x * blockDim.x + threadIdx.x;
    if (i < N_ * N_) g_CP[i] = roundtf(DT_ * A[i]);
}

// ---------------- tf32 tensor-core GEMM: cp.async x3 + ldmatrix, BK=32 -------
// C = alpha*A*op(B) + beta*R (RESID) + R2[row%512] (RESID2)
// A: M x K (lda). NT: B is Nn x K (ldb), C = A*B^T. NN: B is K x Nn (ldb).
// CVT_A/CVT_B: operand needs tf32 rounding. ROUND_C: store C tf32-rounded.
// RMOD>0: residual row = row % RMOD. Warp tile 64 x (BN/WN).
template <int BM, int BN, int WM, int WN, bool TRANS_B, bool RESID, int RMOD,
          bool CVT_A, bool CVT_B, bool ROUND_C, bool RESID2, int KBT, int OCC>
__global__ __launch_bounds__(WM* WN * 32, OCC) void gemm_tc(
    const float* __restrict__ A, const float* __restrict__ Bm,
    float* __restrict__ C, const float* __restrict__ R,
    const float* __restrict__ R2,
    int M, int Nn, int K, int lda, int ldb, int ldc, int ldr,
    long sA, long sB, long sC, long sR, float alpha, float beta) {
    constexpr int STAGES = 3;
    constexpr int NTH = WM * WN * 32;
    constexpr int WTM = BM / WM;           // 64
    constexpr int WTN = BN / WN;           // 32
    constexpr int FM = WTM / 16;           // 4
    constexpr int FN = WTN / 8;            // 4
    constexpr int KQ = KBT / 4;            // 16B chunks per row (8)
    constexpr int LDA_S = KBT + 4;         // 36 words: conflict-free
    constexpr int LDB_S = BN + 8;
    constexpr int NA = BM * KBT / (4 * NTH);
    constexpr int NB = BN * KBT / (4 * NTH);
    constexpr int A_STAGE_B = BM * LDA_S * 4;
    constexpr int BT_STAGE_B = BN * LDA_S * 4;
    constexpr int BN_STAGE_B = KBT * LDB_S * 4;

    extern __shared__ __align__(16) float smem[];
    float* Bs_ = smem + STAGES * BM * LDA_S;
    const uint32_t smem_u32 = (uint32_t)__cvta_generic_to_shared(smem);
    const uint32_t bs_u32 = smem_u32 + STAGES * A_STAGE_B;

    const int bz = blockIdx.z;
    A += (long)bz * sA;
    Bm += (long)bz * sB;
    C += (long)bz * sC;
    if (RESID) R += (long)bz * sR;

    const int row0 = blockIdx.y * BM, col0 = blockIdx.x * BN;
    const int tid = threadIdx.x;
    const int lane = tid & 31, wid = tid >> 5;
    const int grp = lane >> 2, qid = lane & 3;
    const int wm = wid / WN, wn = wid % WN;
    const int m_base = wm * WTM, n_base = wn * WTN;

    const int mi = lane >> 3, rr = lane & 7;
    const uint32_t aAddr0 = smem_u32 +
        (((m_base + ((mi & 1) << 3) + rr) * LDA_S + ((mi >> 1) << 2)) << 2);
    const uint32_t bAddr0 = bs_u32 +
        (((n_base + ((mi >> 1) << 3) + rr) * LDA_S + ((mi & 1) << 2)) << 2);

    float acc[FM][FN][4] = {};

    auto issue = [&](int st, int k0) {
#pragma unroll
        for (int l = 0; l < NA; l++) {
            int i = tid + l * NTH;
            int r = i / KQ, kq = i % KQ;
            cp_async16(smem_u32 + st * A_STAGE_B + ((r * LDA_S + kq * 4) << 2),
                       A + (long)(row0 + r) * lda + k0 + kq * 4);
        }
#pragma unroll
        for (int l = 0; l < NB; l++) {
            int i = tid + l * NTH;
            if (!TRANS_B) {
                int kk = i / (BN / 4), nq = i % (BN / 4);
                cp_async16(bs_u32 + st * BN_STAGE_B + ((kk * LDB_S + nq * 4) << 2),
                           Bm + (long)(k0 + kk) * ldb + col0 + nq * 4);
            } else {
                int n = i / KQ, kq = i % KQ;
                cp_async16(bs_u32 + st * BT_STAGE_B + ((n * LDA_S + kq * 4) << 2),
                           Bm + (long)(col0 + n) * ldb + k0 + kq * 4);
            }
        }
    };

    const int kt = K / KBT;
#pragma unroll
    for (int s = 0; s < STAGES - 1; s++) {
        issue(s, s * KBT);
        asm volatile("cp.async.commit_group;\n");
    }

    for (int t = 0; t < kt; t++) {
        asm volatile("cp.async.wait_group %0;\n" :: "n"(STAGES - 2));
        __syncthreads();
        const int st = t % STAGES;
        const int nx = t + STAGES - 1;
        if (nx < kt) issue(nx % STAGES, nx * KBT);
        asm volatile("cp.async.commit_group;\n");

        const uint32_t aSt = aAddr0 + st * A_STAGE_B;
        const uint32_t bSt = bAddr0 + st * BT_STAGE_B;

#pragma unroll
        for (int kc = 0; kc < KBT / 8; kc++) {
            const int kk = kc * 8;
            uint32_t af[FM][4], bf[FN][2];
#pragma unroll
            for (int i = 0; i < FM; i++) {
                ldsm_x4(af[i], aSt + i * (16 * LDA_S * 4) + kc * 32);
                if (CVT_A) {
#pragma unroll
                    for (int q = 0; q < 4; q++) af[i][q] = f2tf32(__uint_as_float(af[i][q]));
                }
            }
            if (TRANS_B) {
#pragma unroll
                for (int jp = 0; jp < FN / 2; jp++) {
                    uint32_t tmp4[4];
                    ldsm_x4(tmp4, bSt + jp * (16 * LDA_S * 4) + kc * 32);
                    if (CVT_B) {
#pragma unroll
                        for (int q = 0; q < 4; q++) tmp4[q] = f2tf32(__uint_as_float(tmp4[q]));
                    }
                    bf[jp * 2][0] = tmp4[0]; bf[jp * 2][1] = tmp4[1];
                    bf[jp * 2 + 1][0] = tmp4[2]; bf[jp * 2 + 1][1] = tmp4[3];
                }
            } else {
#pragma unroll
                for (int j = 0; j < FN; j++) {
                    int n = n_base + j * 8 + grp;
                    float b0 = Bs_[(st * KBT + kk + qid) * LDB_S + n];
                    float b1 = Bs_[(st * KBT + kk + qid + 4) * LDB_S + n];
                    bf[j][0] = CVT_B ? f2tf32(b0) : __float_as_uint(b0);
                    bf[j][1] = CVT_B ? f2tf32(b1) : __float_as_uint(b1);
                }
            }
#pragma unroll
            for (int i = 0; i < FM; i++)
#pragma unroll
                for (int j = 0; j < FN; j++) mma_tf32(acc[i][j], af[i], bf[j]);
        }
    }

    // ---- epilogue ----
#pragma unroll
    for (int i = 0; i < FM; i++) {
        int r0 = row0 + m_base + i * 16 + grp;
#pragma unroll
        for (int j = 0; j < FN; j++) {
            int c = col0 + n_base + j * 8 + qid * 2;
            float2 v0 = {acc[i][j][0] * alpha, acc[i][j][1] * alpha};
            float2 v1 = {acc[i][j][2] * alpha, acc[i][j][3] * alpha};
            if (RESID) {
                int rr0 = RMOD ? (r0 % RMOD) : r0;
                int rr1 = RMOD ? ((r0 + 8) % RMOD) : (r0 + 8);
                float2 r0v = *(const float2*)(R + (long)rr0 * ldr + c);
                float2 r1v = *(const float2*)(R + (long)rr1 * ldr + c);
                v0.x += beta * r0v.x; v0.y += beta * r0v.y;
                v1.x += beta * r1v.x; v1.y += beta * r1v.y;
            }
            if (RESID2) {
                float2 a0 = *(const float2*)(R2 + (long)(r0 % N_) * N_ + c);
                float2 a1 = *(const float2*)(R2 + (long)((r0 + 8) % N_) * N_ + c);
                v0.x += a0.x; v0.y += a0.y;
                v1.x += a1.x; v1.y += a1.y;
            }
            if (ROUND_C) {
                v0.x = roundtf(v0.x); v0.y = roundtf(v0.y);
                v1.x = roundtf(v1.x); v1.y = roundtf(v1.y);
            }
            *(float2*)(C + (long)r0 * ldc + c) = v0;
            *(float2*)(C + (long)(r0 + 8) * ldc + c) = v1;
        }
    }
}

// host-side smem size mirror (BK=32, 3 stages)
static inline int gemm_smem_bytes(int BM, int BN, bool transB) {
    const int STAGES = 3, KBT = 32, LDA_S = KBT + 4;
    int a = STAGES * BM * LDA_S;
    int b = transB ? STAGES * BN * LDA_S : STAGES * KBT * (BN + 8);
    return (a + b) * 4;
}

// ---------------- row softmax over 512, output tf32-rounded -----------------
__global__ __launch_bounds__(256) void softmax_kernel() {
    long row = (long)blockIdx.x * 8 + (threadIdx.x >> 5);
    int lane = threadIdx.x & 31;
    if (row >= (long)B_ * Q_ * N_) return;
    float* p = g_S + row * N_;
    float vals[16];
    float m = -1e30f;
#pragma unroll
    for (int i = 0; i < 16; i++) {
        vals[i] = p[lane + i * 32];
        m = fmaxf(m, vals[i]);
    }
#pragma unroll
    for (int o = 16; o; o >>= 1) m = fmaxf(m, __shfl_xor_sync(0xffffffffu, m, o));
    float s = 0.f;
#pragma unroll
    for (int i = 0; i < 16; i++) {
        vals[i] = __expf(vals[i] - m);
        s += vals[i];
    }
#pragma unroll
    for (int o = 16; o; o >>= 1) s += __shfl_xor_sync(0xffffffffu, s, o);
    float inv = 1.f / s;
#pragma unroll
    for (int i = 0; i < 16; i++) p[lane + i * 32] = roundtf(vals[i] * inv);
}

// ---------------- launch ----------------------------------------------------
extern "C" void kernel_launch(void* const* d_in, const int* in_sizes, int n_in,
                              void* d_out, int out_size) {
    const float* inputs = (const float*)d_in[0];
    const float* W_in  = (const float*)d_in[2];
    const float* T_mix = (const float*)d_in[3];
    const float* Wq    = (const float*)d_in[4];
    const float* Wk    = (const float*)d_in[5];
    const float* Wv    = (const float*)d_in[6];
    const float* W_out = (const float*)d_in[7];
    const float* A     = (const float*)d_in[8];

    float* out = (float*)d_out;
    float* mgt = out;
    float* kal = out + (long)B_ * Q_ * N_ * F_;

    float *tmp, *h, *qkv, *S, *CP, *WinT, *WqkvT, *WoutT;
    cudaGetSymbolAddress((void**)&tmp, g_tmp);
    cudaGetSymbolAddress((void**)&h, g_h);
    cudaGetSymbolAddress((void**)&qkv, g_qkv);
    cudaGetSymbolAddress((void**)&S, g_S);
    cudaGetSymbolAddress((void**)&CP, g_CP);
    cudaGetSymbolAddress((void**)&WinT, g_WinT);
    cudaGetSymbolAddress((void**)&WqkvT, g_WqkvT);
    cudaGetSymbolAddress((void**)&WoutT, g_WoutT);

    const long sNN = (long)N_ * N_;
    const long sNF = (long)N_ * F_;
    const long sQKV = (long)N_ * 3 * D_;
    const long sH = (long)N_ * D_;

    // GEMM instances: BN=128, warp tile 64x32, 2 CTAs/SM, BK=32
    auto kNT   = gemm_tc<128, 128, 2, 4, true,  false, 0,  false, false, true,  false, 32, 2>;
    auto kNT_S = gemm_tc<128, 128, 2, 4, true,  false, 0,  false, false, false, false, 32, 2>;
    auto kNN_R = gemm_tc<128, 128, 2, 4, false, true,  0,  false, false, true,  false, 32, 2>;
    auto kOUT  = gemm_tc<128, 64,  2, 2, true,  false, 0,  false, false, false, false, 32, 2>;
    auto kCP   = gemm_tc<128, 128, 2, 4, false, true,  0,  false, false, true,  true,  32, 2>;
    auto kKAL  = gemm_tc<128, 64,  2, 2, false, true,  N_, false, true,  false, false, 32, 2>;

    const int smNT   = gemm_smem_bytes(128, 128, true);
    const int smNN   = gemm_smem_bytes(128, 128, false);
    const int smNT64 = gemm_smem_bytes(128, 64, true);
    const int smNN64 = gemm_smem_bytes(128, 64, false);
    cudaFuncSetAttribute(kNT,   cudaFuncAttributeMaxDynamicSharedMemorySize, smNT);
    cudaFuncSetAttribute(kNT_S, cudaFuncAttributeMaxDynamicSharedMemorySize, smNT);
    cudaFuncSetAttribute(kNN_R, cudaFuncAttributeMaxDynamicSharedMemorySize, smNN);
    cudaFuncSetAttribute(kOUT,  cudaFuncAttributeMaxDynamicSharedMemorySize, smNT64);
    cudaFuncSetAttribute(kCP,   cudaFuncAttributeMaxDynamicSharedMemorySize, smNN);
    cudaFuncSetAttribute(kKAL,  cudaFuncAttributeMaxDynamicSharedMemorySize, smNN64);

    // K1 + setup
    mix_kernel<<<((long)B_ * N_ * F_ + 255) / 256, 256>>>(inputs, T_mix);
    prep_weights<<<(D_ * D_ + 255) / 256, 256>>>(W_in, Wq, Wk, Wv, W_out);
    scaleA_kernel<<<(N_ * N_ + 255) / 256, 256>>>(A);   // c1 = tf32(DT*A)

    // CP chain: c_{k+j} = c_k @ c_j + c_k + c_j  (log-depth, 4 launches)
    float* c1 = CP;
    float* c2 = CP + sNN;
    float* c4 = CP + 3 * sNN;
    float* c8 = CP + 7 * sNN;
    kCP<<<dim3(4, 4, 1), 256, smNN>>>(c1, c1, c2, c1, c1,
        N_, N_, N_, N_, N_, N_, N_, 0, 0, 0, 0, 1.f, 1.f);
    kCP<<<dim3(4, 8, 1), 256, smNN>>>(CP, c2, CP + 2 * sNN, CP, c2,
        2 * N_, N_, N_, N_, N_, N_, N_, 0, 0, 0, 0, 1.f, 1.f);
    kCP<<<dim3(4, 16, 1), 256, smNN>>>(CP, c4, CP + 4 * sNN, CP, c4,
        4 * N_, N_, N_, N_, N_, N_, N_, 0, 0, 0, 0, 1.f, 1.f);
    kCP<<<dim3(4, 16, 1), 256, smNN>>>(CP, c8, CP + 8 * sNN, CP, c8,
        4 * N_, N_, N_, N_, N_, N_, N_, 0, 0, 0, 0, 1.f, 1.f);

    // K2: h = tmp @ WinT^T
    kNT<<<dim3(2, BQN / 128, 1), 256, smNT>>>(
        tmp, WinT, h, nullptr, nullptr,
        BQN, D_, F_, F_, F_, D_, 0, 0, 0, 0, 0, 1.f, 0.f);

    // K3: qkv = h @ WqkvT^T
    kNT<<<dim3(6, BQN / 128, 1), 256, smNT>>>(
        h, WqkvT, qkv, nullptr, nullptr,
        BQN, 3 * D_, D_, D_, D_, 3 * D_, 0, 0, 0, 0, 0, 1.f, 0.f);

    // K4: S = q @ k^T  batched (NT), raw fp32 scores
    kNT_S<<<dim3(4, 4, NBQ), 256, smNT>>>(
        qkv, qkv + D_, S, nullptr, nullptr,
        N_, N_, D_, 3 * D_, 3 * D_, N_, 0, sQKV, sQKV, sNN, 0, 1.f, 0.f);

    // K5: softmax (rounds attn to tf32)
    softmax_kernel<<<(BQN + 7) / 8, 256>>>();

    // K6: h = h + attn @ v  batched (NN, residual)
    kNN_R<<<dim3(2, 4, NBQ), 256, smNN>>>(
        S, qkv + 2 * D_, h, h, nullptr,
        N_, D_, N_, N_, 3 * D_, D_, D_, sNN, sQKV, sH, sH, 1.f, 1.f);

    // K7: mgt = h @ WoutT^T
    kOUT<<<dim3(1, BQN / 128, 1), 128, smNT64>>>(
        h, WoutT, mgt, nullptr, nullptr,
        BQN, F_, D_, D_, D_, F_, 0, 0, 0, 0, 0, 1.f, 0.f);

    // Kalman (single parallel launch): kal[b, t] = c_{t+1} @ mu0[b] + mu0[b]
    const float* mu0 = inputs + (long)(P_ - 1) * sNF;
    kKAL<<<dim3(1, 12 * N_ / 128, B_), 128, smNN64>>>(
        CP, mu0, kal, mu0, nullptr,
        12 * N_, F_, N_, N_, F_, F_, F_,
        0, (long)P_ * sNF, (long)Q_ * sNF, (long)P_ * sNF, 1.f, 1.f);
}